// round 2
// baseline (speedup 1.0000x reference)
#include <cuda_runtime.h>
#include <cuda_bf16.h>

#define LQ 50
#define LK 200
#define DIM 128
#define KST 129          // padded K/V row stride (bank-conflict-free scalar access)
#define NTH 512
#define NWARP 16
#define NQG 13           // ceil(50/4) query groups of 4

// smem layout (floats): [0, LK*KST) K/V buffer, then Q [LQ*DIM], then S [LQ*LK]
#define SMEM_FLOATS (LK*KST + LQ*DIM + LQ*LK)

__global__ void __launch_bounds__(NTH, 1)
attn_kernel(const int* __restrict__ Qi, const int* __restrict__ Ki,
            const int* __restrict__ Vi,
            const float* __restrict__ Wq, const float* __restrict__ Wk,
            const float* __restrict__ Wv,
            const float* __restrict__ gamma, const float* __restrict__ beta,
            const float* __restrict__ eps, float* __restrict__ out)
{
    extern __shared__ float smem[];
    float* sKV = smem;                 // LK * KST
    float* sQ  = smem + LK * KST;      // LQ * DIM
    float* sS  = sQ + LQ * DIM;        // LQ * LK

    const int b    = blockIdx.x;
    const int tid  = threadIdx.x;
    const int warp = tid >> 5;
    const int lane = tid & 31;

    // ---- gather K rows into smem (stride KST), Q rows (stride DIM) ----
    {
        const int* kidx = Ki + b * LK;
        for (int i = tid; i < LK * DIM; i += NTH) {
            int r = i >> 7, c = i & 127;
            sKV[r * KST + c] = Wk[(size_t)kidx[r] * DIM + c];
        }
        const int* qidx = Qi + b * LQ;
        for (int i = tid; i < LQ * DIM; i += NTH) {
            int r = i >> 7;
            sQ[i] = Wq[(size_t)qidx[r] * DIM + (i & 127)];
        }
    }
    __syncthreads();

    // ---- S = Q K^T / sqrt(d) : warp handles 4 queries, lane owns keys lane+32j ----
    const float scale = 0.08838834764831845f; // 1/sqrt(128)
    for (int qg = warp; qg < NQG; qg += NWARP) {
        const int q0 = qg * 4;
        const float* qrow0 = sQ + min(q0 + 0, LQ - 1) * DIM;
        const float* qrow1 = sQ + min(q0 + 1, LQ - 1) * DIM;
        const float* qrow2 = sQ + min(q0 + 2, LQ - 1) * DIM;
        const float* qrow3 = sQ + min(q0 + 3, LQ - 1) * DIM;
        float acc[4][7];
        #pragma unroll
        for (int qi = 0; qi < 4; qi++)
            #pragma unroll
            for (int j = 0; j < 7; j++) acc[qi][j] = 0.f;

        #pragma unroll 4
        for (int c = 0; c < DIM; ++c) {
            float kv[7];
            #pragma unroll
            for (int j = 0; j < 6; j++)
                kv[j] = sKV[(lane + 32 * j) * KST + c];
            kv[6] = (lane < 8) ? sKV[(lane + 192) * KST + c] : 0.f;
            const float q0v = qrow0[c], q1v = qrow1[c], q2v = qrow2[c], q3v = qrow3[c];
            #pragma unroll
            for (int j = 0; j < 7; j++) {
                acc[0][j] = fmaf(q0v, kv[j], acc[0][j]);
                acc[1][j] = fmaf(q1v, kv[j], acc[1][j]);
                acc[2][j] = fmaf(q2v, kv[j], acc[2][j]);
                acc[3][j] = fmaf(q3v, kv[j], acc[3][j]);
            }
        }
        const int nq = min(4, LQ - q0);
        for (int qi = 0; qi < nq; qi++) {
            #pragma unroll
            for (int j = 0; j < 7; j++) {
                int k = lane + 32 * j;
                if (k < LK) sS[(q0 + qi) * LK + k] = acc[qi][j] * scale;
            }
        }
    }
    __syncthreads();

    // ---- overwrite sKV with gathered V rows (QK phase done) ----
    {
        const int* vidx = Vi + b * LK;
        for (int i = tid; i < LK * DIM; i += NTH) {
            int r = i >> 7, c = i & 127;
            sKV[r * KST + c] = Wv[(size_t)vidx[r] * DIM + c];
        }
    }

    // ---- weight = softmax(S + eps_noise) per (q) row; one warp per row ----
    for (int q = warp; q < LQ; q += NWARP) {
        const float* er = eps + ((size_t)b * LQ + q) * LK;
        float v[7];
        float m = -1e30f;
        #pragma unroll
        for (int j = 0; j < 7; j++) {
            int k = lane + 32 * j;
            if (k < LK) {
                v[j] = sS[q * LK + k] + er[k];
                m = fmaxf(m, v[j]);
            } else v[j] = -1e30f;
        }
        #pragma unroll
        for (int off = 16; off >= 1; off >>= 1)
            m = fmaxf(m, __shfl_xor_sync(0xffffffffu, m, off));
        float s = 0.f;
        #pragma unroll
        for (int j = 0; j < 7; j++) {
            int k = lane + 32 * j;
            if (k < LK) { v[j] = __expf(v[j] - m); s += v[j]; }
        }
        #pragma unroll
        for (int off = 16; off >= 1; off >>= 1)
            s += __shfl_xor_sync(0xffffffffu, s, off);
        const float inv = 1.f / s;
        #pragma unroll
        for (int j = 0; j < 7; j++) {
            int k = lane + 32 * j;
            if (k < LK) sS[q * LK + k] = v[j] * inv;
        }
    }
    __syncthreads();

    // ---- context = W @ V, then LayerNorm; lane owns dims lane+32m ----
    for (int qg = warp; qg < NQG; qg += NWARP) {
        const int q0 = qg * 4;
        const int nq = min(4, LQ - q0);
        const float* wrow0 = sS + min(q0 + 0, LQ - 1) * LK;
        const float* wrow1 = sS + min(q0 + 1, LQ - 1) * LK;
        const float* wrow2 = sS + min(q0 + 2, LQ - 1) * LK;
        const float* wrow3 = sS + min(q0 + 3, LQ - 1) * LK;
        float acc[4][4];
        #pragma unroll
        for (int qi = 0; qi < 4; qi++)
            #pragma unroll
            for (int m2 = 0; m2 < 4; m2++) acc[qi][m2] = 0.f;

        #pragma unroll 2
        for (int k = 0; k < LK; ++k) {
            float vv[4];
            #pragma unroll
            for (int m2 = 0; m2 < 4; m2++)
                vv[m2] = sKV[k * KST + lane + 32 * m2];
            const float w0 = wrow0[k], w1 = wrow1[k], w2 = wrow2[k], w3 = wrow3[k];
            #pragma unroll
            for (int m2 = 0; m2 < 4; m2++) {
                acc[0][m2] = fmaf(w0, vv[m2], acc[0][m2]);
                acc[1][m2] = fmaf(w1, vv[m2], acc[1][m2]);
                acc[2][m2] = fmaf(w2, vv[m2], acc[2][m2]);
                acc[3][m2] = fmaf(w3, vv[m2], acc[3][m2]);
            }
        }

        for (int qi = 0; qi < nq; qi++) {
            const int q = q0 + qi;
            // mean over 128 dims (lane holds 4)
            float lsum = acc[qi][0] + acc[qi][1] + acc[qi][2] + acc[qi][3];
            #pragma unroll
            for (int off = 16; off >= 1; off >>= 1)
                lsum += __shfl_xor_sync(0xffffffffu, lsum, off);
            const float mu = lsum * (1.f / 128.f);
            float lvar = 0.f;
            #pragma unroll
            for (int m2 = 0; m2 < 4; m2++) {
                float d = acc[qi][m2] - mu;
                lvar = fmaf(d, d, lvar);
            }
            #pragma unroll
            for (int off = 16; off >= 1; off >>= 1)
                lvar += __shfl_xor_sync(0xffffffffu, lvar, off);
            const float rstd = rsqrtf(lvar * (1.f / 128.f) + 1e-5f);
            float* orow = out + ((size_t)b * LQ + q) * DIM;
            #pragma unroll
            for (int m2 = 0; m2 < 4; m2++) {
                int d = lane + 32 * m2;
                orow[d] = (acc[qi][m2] - mu) * rstd * gamma[d] + beta[d];
            }
        }
    }
}

extern "C" void kernel_launch(void* const* d_in, const int* in_sizes, int n_in,
                              void* d_out, int out_size)
{
    const int*   Qi    = (const int*)d_in[0];
    const int*   Ki    = (const int*)d_in[1];
    const int*   Vi    = (const int*)d_in[2];
    const float* Wq    = (const float*)d_in[3];
    const float* Wk    = (const float*)d_in[4];
    const float* Wv    = (const float*)d_in[5];
    const float* gamma = (const float*)d_in[6];
    const float* beta  = (const float*)d_in[7];
    const float* eps   = (const float*)d_in[8];
    float* out = (float*)d_out;

    const int batch = in_sizes[0] / LQ;   // 256
    const size_t smem_bytes = (size_t)SMEM_FLOATS * sizeof(float);
    cudaFuncSetAttribute(attn_kernel, cudaFuncAttributeMaxDynamicSharedMemorySize,
                         (int)smem_bytes);
    attn_kernel<<<batch, NTH, smem_bytes>>>(Qi, Ki, Vi, Wq, Wk, Wv, gamma, beta,
                                            eps, out);
}